// round 2
// baseline (speedup 1.0000x reference)
#include <cuda_runtime.h>
#include <cstdint>

// instant-ngp HashEncoder forward: D=3, L=16, C=2, base_res=16, scale=2, 2^19 hashmap.
// Levels 0..2 dense (res^3 entries), levels 3..15 hashed (2^19 entries, power-of-2 -> mask).
// Replicates reference arithmetic exactly (uint32 hash/stride math, no clamping).

#define PRIME_Y 2654435761u
#define PRIME_Z 805459861u
#define HASH_MASK 524287u  // 2^19 - 1

__global__ __launch_bounds__(256) void hashenc_fwd(
    const float* __restrict__ inp,   // [B, 3]
    const float2* __restrict__ emb,  // [TOTAL_PARAMS] as float2 (C=2)
    float* __restrict__ out,         // [B, 32]
    int B)
{
    const int b = blockIdx.x * blockDim.x + threadIdx.x;
    if (b >= B) return;

    // normalize [-1,1] -> [0,1]
    const float x = (inp[3 * b + 0] + 1.0f) * 0.5f;
    const float y = (inp[3 * b + 1] + 1.0f) * 0.5f;
    const float z = (inp[3 * b + 2] + 1.0f) * 0.5f;

    // level offsets into the embedding table (elements of float2)
    const uint32_t OFF[16] = {
        0u, 4096u, 36864u, 299008u, 823296u, 1347584u, 1871872u, 2396160u,
        2920448u, 3444736u, 3969024u, 4493312u, 5017600u, 5541888u, 6066176u, 6590464u
    };

    float acc[32];

#pragma unroll
    for (int l = 0; l < 16; ++l) {
        const uint32_t res = 16u << l;          // exact: ceil(16 * 2^l)
        const float scale = (float)res - 1.0f;  // base*pls^l - 1

        const float px = x * scale + 0.5f;
        const float py = y * scale + 0.5f;
        const float pz = z * scale + 0.5f;

        const float gx = floorf(px);
        const float gy = floorf(py);
        const float gz = floorf(pz);

        const float tx = px - gx;
        const float ty = py - gy;
        const float tz = pz - gz;

        const uint32_t ix = (uint32_t)gx;
        const uint32_t iy = (uint32_t)gy;
        const uint32_t iz = (uint32_t)gz;

        uint32_t hx[2], hy[2], hz[2];
        if (l < 3) {
            // dense: row-major strides [1, res, res*res] (uint32 math, like the reference)
            hx[0] = ix;             hx[1] = ix + 1u;
            hy[0] = iy * res;       hy[1] = (iy + 1u) * res;
            hz[0] = iz * res * res; hz[1] = (iz + 1u) * (res * res);
        } else {
            // hashed: xor of per-dim (coord * prime), prime_x = 1
            hx[0] = ix;             hx[1] = ix + 1u;
            hy[0] = iy * PRIME_Y;   hy[1] = (iy + 1u) * PRIME_Y;
            hz[0] = iz * PRIME_Z;   hz[1] = (iz + 1u) * PRIME_Z;
        }

        const float wx[2] = {1.0f - tx, tx};
        const float wy[2] = {1.0f - ty, ty};
        const float wz[2] = {1.0f - tz, tz};

        float sx = 0.0f, sy = 0.0f;
#pragma unroll
        for (int c = 0; c < 8; ++c) {
            const int bx = c & 1, by = (c >> 1) & 1, bz = (c >> 2) & 1;
            uint32_t idx;
            if (l < 3) idx = hx[bx] + hy[by] + hz[bz];
            else       idx = (hx[bx] ^ hy[by] ^ hz[bz]) & HASH_MASK;
            const float w = wx[bx] * wy[by] * wz[bz];
            const float2 g = __ldg(&emb[OFF[l] + idx]);
            sx = fmaf(w, g.x, sx);
            sy = fmaf(w, g.y, sy);
        }
        acc[2 * l + 0] = sx;
        acc[2 * l + 1] = sy;
    }

    // coalesced 128B-per-thread store
    float4* o4 = (float4*)(out + (size_t)b * 32);
#pragma unroll
    for (int i = 0; i < 8; ++i) {
        o4[i] = make_float4(acc[4 * i + 0], acc[4 * i + 1], acc[4 * i + 2], acc[4 * i + 3]);
    }
}

extern "C" void kernel_launch(void* const* d_in, const int* in_sizes, int n_in,
                              void* d_out, int out_size)
{
    // inputs: [B,3] f32 (3,145,728 elems); embeddings: [7114752, 2] f32 (14,229,504 elems)
    const float* p0 = (const float*)d_in[0];
    const float* p1 = (const float*)d_in[1];
    const float* inp;
    const float* emb;
    int B;
    if (in_sizes[0] < in_sizes[1]) {
        inp = p0; emb = p1; B = in_sizes[0] / 3;
    } else {
        inp = p1; emb = p0; B = in_sizes[1] / 3;
    }
    const int threads = 256;
    const int blocks = (B + threads - 1) / threads;
    hashenc_fwd<<<blocks, threads>>>(inp, (const float2*)emb, (float*)d_out, B);
}

// round 4
// speedup vs baseline: 1.9637x; 1.9637x over previous
#include <cuda_runtime.h>
#include <cstdint>

// instant-ngp HashEncoder forward: D=3, L=16, C=2, base_res=16, scale=2, 2^19 hashmap.
// Levels 0..2 dense, levels 3..15 hashed (2^19 entries -> mask).
// Optimization: for each (by,bz) corner pair, when the two x-corner indices
// differ only in bit 0 (i0^i1==1), fetch both with ONE 16B float4 load
// (one L1 wavefront instead of two). Happens 50% of the time on every level.

#define PRIME_Y 2654435761u
#define PRIME_Z 805459861u
#define HASH_MASK 524287u  // 2^19 - 1

__global__ __launch_bounds__(256) void hashenc_fwd(
    const float* __restrict__ inp,   // [B, 3]
    const float* __restrict__ emb,   // [TOTAL_PARAMS * 2] scalar float view
    float* __restrict__ out,         // [B, 32]
    int B)
{
    const int b = blockIdx.x * blockDim.x + threadIdx.x;
    if (b >= B) return;

    // normalize [-1,1] -> [0,1]
    const float x = (inp[3 * b + 0] + 1.0f) * 0.5f;
    const float y = (inp[3 * b + 1] + 1.0f) * 0.5f;
    const float z = (inp[3 * b + 2] + 1.0f) * 0.5f;

    // level offsets (in float2 elements)
    const uint32_t OFF[16] = {
        0u, 4096u, 36864u, 299008u, 823296u, 1347584u, 1871872u, 2396160u,
        2920448u, 3444736u, 3969024u, 4493312u, 5017600u, 5541888u, 6066176u, 6590464u
    };

    float acc[32];

#pragma unroll
    for (int l = 0; l < 16; ++l) {
        const uint32_t res = 16u << l;
        const float scale = (float)res - 1.0f;

        const float px = x * scale + 0.5f;
        const float py = y * scale + 0.5f;
        const float pz = z * scale + 0.5f;

        const float gx = floorf(px);
        const float gy = floorf(py);
        const float gz = floorf(pz);

        const float tx = px - gx;
        const float ty = py - gy;
        const float tz = pz - gz;

        const uint32_t ix = (uint32_t)gx;
        const uint32_t iy = (uint32_t)gy;
        const uint32_t iz = (uint32_t)gz;

        // per-dim components for y/z corners (0 and +1)
        uint32_t cy[2], cz[2];
        if (l < 3) {
            cy[0] = iy * res;       cy[1] = (iy + 1u) * res;
            cz[0] = iz * res * res; cz[1] = (iz + 1u) * (res * res);
        } else {
            cy[0] = iy * PRIME_Y;   cy[1] = (iy + 1u) * PRIME_Y;
            cz[0] = iz * PRIME_Z;   cz[1] = (iz + 1u) * PRIME_Z;
        }

        const float wy[2] = {1.0f - ty, ty};
        const float wz[2] = {1.0f - tz, tz};

        const float* lvl = emb + 2u * OFF[l];

        float sx = 0.0f, sy = 0.0f;
#pragma unroll
        for (int c = 0; c < 4; ++c) {
            const int by = c & 1, bz = (c >> 1) & 1;

            uint32_t i0, i1;
            if (l < 3) {
                i0 = ix + cy[by] + cz[bz];
                i1 = i0 + 1u;
            } else {
                const uint32_t m = cy[by] ^ cz[bz];
                i0 = (ix ^ m) & HASH_MASK;
                i1 = ((ix + 1u) ^ m) & HASH_MASK;
            }

            float2 g0, g1;
            if ((i0 ^ i1) == 1u) {
                // both corners live in one 16B-aligned float4: one wavefront
                const float4 g4 = __ldg((const float4*)(lvl + 2u * (i0 & ~1u)));
                if (i0 & 1u) { g0 = make_float2(g4.z, g4.w); g1 = make_float2(g4.x, g4.y); }
                else         { g0 = make_float2(g4.x, g4.y); g1 = make_float2(g4.z, g4.w); }
            } else {
                g0 = __ldg((const float2*)(lvl + 2u * i0));
                g1 = __ldg((const float2*)(lvl + 2u * i1));
            }

            const float wyz = wy[by] * wz[bz];
            const float w1 = tx * wyz;
            const float w0 = wyz - w1;
            sx = fmaf(w0, g0.x, fmaf(w1, g1.x, sx));
            sy = fmaf(w0, g0.y, fmaf(w1, g1.y, sy));
        }
        acc[2 * l + 0] = sx;
        acc[2 * l + 1] = sy;
    }

    // coalesced 128B-per-thread store
    float4* o4 = (float4*)(out + (size_t)b * 32);
#pragma unroll
    for (int i = 0; i < 8; ++i) {
        o4[i] = make_float4(acc[4 * i + 0], acc[4 * i + 1], acc[4 * i + 2], acc[4 * i + 3]);
    }
}

extern "C" void kernel_launch(void* const* d_in, const int* in_sizes, int n_in,
                              void* d_out, int out_size)
{
    const float* p0 = (const float*)d_in[0];
    const float* p1 = (const float*)d_in[1];
    const float* inp;
    const float* emb;
    int B;
    if (in_sizes[0] < in_sizes[1]) {
        inp = p0; emb = p1; B = in_sizes[0] / 3;
    } else {
        inp = p1; emb = p0; B = in_sizes[1] / 3;
    }
    const int threads = 256;
    const int blocks = (B + threads - 1) / threads;
    hashenc_fwd<<<blocks, threads>>>(inp, emb, (float*)d_out, B);
}

// round 5
// speedup vs baseline: 2.0309x; 1.0342x over previous
#include <cuda_runtime.h>
#include <cstdint>

// instant-ngp HashEncoder forward: D=3, L=16, C=2, base=16, scale=2, 2^19 hashmap.
// Levels 0..2 dense, 3..15 hashed (2^19 -> mask).
// R4: (a) rolling float4 output chunk (no acc[32]) + __launch_bounds__(256,6)
//     to lift occupancy 47% -> ~75%;
//     (b) pair-merge predicate hoisted: merge iff ix even (uniform per level).

#define PRIME_Y 2654435761u
#define PRIME_Z 805459861u
#define HASH_MASK 524287u  // 2^19 - 1

__global__ __launch_bounds__(256, 6) void hashenc_fwd(
    const float* __restrict__ inp,   // [B, 3]
    const float* __restrict__ emb,   // [TOTAL_PARAMS * 2] scalar float view
    float* __restrict__ out,         // [B, 32]
    int B)
{
    const int b = blockIdx.x * blockDim.x + threadIdx.x;
    if (b >= B) return;

    const float x = (inp[3 * b + 0] + 1.0f) * 0.5f;
    const float y = (inp[3 * b + 1] + 1.0f) * 0.5f;
    const float z = (inp[3 * b + 2] + 1.0f) * 0.5f;

    // level offsets (in float2 elements)
    const uint32_t OFF[16] = {
        0u, 4096u, 36864u, 299008u, 823296u, 1347584u, 1871872u, 2396160u,
        2920448u, 3444736u, 3969024u, 4493312u, 5017600u, 5541888u, 6066176u, 6590464u
    };

    float4* o4 = (float4*)(out + (size_t)b * 32);
    float4 chunk;

#pragma unroll
    for (int l = 0; l < 16; ++l) {
        const uint32_t res = 16u << l;
        const float scale = (float)res - 1.0f;

        const float px = x * scale + 0.5f;
        const float py = y * scale + 0.5f;
        const float pz = z * scale + 0.5f;

        const float gx = floorf(px);
        const float gy = floorf(py);
        const float gz = floorf(pz);

        const float tx = px - gx;
        const float ty = py - gy;
        const float tz = pz - gz;

        const uint32_t ix = (uint32_t)gx;
        const uint32_t iy = (uint32_t)gy;
        const uint32_t iz = (uint32_t)gz;

        uint32_t cy[2], cz[2];
        if (l < 3) {
            cy[0] = iy * res;       cy[1] = (iy + 1u) * res;
            cz[0] = iz * res * res; cz[1] = (iz + 1u) * (res * res);
        } else {
            cy[0] = iy * PRIME_Y;   cy[1] = (iy + 1u) * PRIME_Y;
            cz[0] = iz * PRIME_Z;   cz[1] = (iz + 1u) * PRIME_Z;
        }

        const float wy[2] = {1.0f - ty, ty};
        const float wz[2] = {1.0f - tz, tz};

        const float* lvl = emb + 2u * OFF[l];

        float sx = 0.0f, sy = 0.0f;

        if ((ix & 1u) == 0u) {
            // x-corner pair always shares a 16B-aligned float4 (one wavefront each)
#pragma unroll
            for (int c = 0; c < 4; ++c) {
                const int by = c & 1, bz = (c >> 1) & 1;
                uint32_t base, sw;
                if (l < 3) {
                    base = ix + cy[by] + cz[bz];   // even
                    sw = 0u;
                } else {
                    const uint32_t i0 = (ix ^ cy[by] ^ cz[bz]) & HASH_MASK;
                    base = i0 & ~1u;
                    sw = i0 & 1u;
                }
                const float4 g4 = __ldg((const float4*)(lvl + 2u * base));
                float2 g0, g1;
                if (sw) { g0 = make_float2(g4.z, g4.w); g1 = make_float2(g4.x, g4.y); }
                else    { g0 = make_float2(g4.x, g4.y); g1 = make_float2(g4.z, g4.w); }

                const float wyz = wy[by] * wz[bz];
                const float w1 = tx * wyz;
                const float w0 = wyz - w1;
                sx = fmaf(w0, g0.x, fmaf(w1, g1.x, sx));
                sy = fmaf(w0, g0.y, fmaf(w1, g1.y, sy));
            }
        } else {
            const uint32_t ix1 = ix + 1u;
#pragma unroll
            for (int c = 0; c < 4; ++c) {
                const int by = c & 1, bz = (c >> 1) & 1;
                uint32_t i0, i1;
                if (l < 3) {
                    i0 = ix + cy[by] + cz[bz];
                    i1 = i0 + 1u;
                } else {
                    const uint32_t m = cy[by] ^ cz[bz];
                    i0 = (ix  ^ m) & HASH_MASK;
                    i1 = (ix1 ^ m) & HASH_MASK;
                }
                const float2 g0 = __ldg((const float2*)(lvl + 2u * i0));
                const float2 g1 = __ldg((const float2*)(lvl + 2u * i1));

                const float wyz = wy[by] * wz[bz];
                const float w1 = tx * wyz;
                const float w0 = wyz - w1;
                sx = fmaf(w0, g0.x, fmaf(w1, g1.x, sx));
                sy = fmaf(w0, g0.y, fmaf(w1, g1.y, sy));
            }
        }

        if (l & 1) {
            chunk.z = sx; chunk.w = sy;
            o4[l >> 1] = chunk;
        } else {
            chunk.x = sx; chunk.y = sy;
        }
    }
}

extern "C" void kernel_launch(void* const* d_in, const int* in_sizes, int n_in,
                              void* d_out, int out_size)
{
    const float* p0 = (const float*)d_in[0];
    const float* p1 = (const float*)d_in[1];
    const float* inp;
    const float* emb;
    int B;
    if (in_sizes[0] < in_sizes[1]) {
        inp = p0; emb = p1; B = in_sizes[0] / 3;
    } else {
        inp = p1; emb = p0; B = in_sizes[1] / 3;
    }
    const int threads = 256;
    const int blocks = (B + threads - 1) / threads;
    hashenc_fwd<<<blocks, threads>>>(inp, emb, (float*)d_out, B);
}